// round 1
// baseline (speedup 1.0000x reference)
#include <cuda_runtime.h>
#include <math.h>

#define MTOK   8192
#define DMODEL 1024
#define TD     3072
#define FFD    4096
#define NHEAD  16
#define DHEAD  64
#define SEQ    2048
#define BATCH  4

// Scratch (no cudaMalloc allowed): 32+96+32+32+128 = 320 MB
__device__ float g_ln  [(size_t)MTOK * DMODEL];
__device__ float g_qkv [(size_t)MTOK * TD];
__device__ float g_attn[(size_t)MTOK * DMODEL];
__device__ float g_h2  [(size_t)MTOK * DMODEL];
__device__ float g_fc  [(size_t)MTOK * FFD];

__device__ __forceinline__ float gelu_new_f(float x) {
    float u = 0.7978845608028654f * (x + 0.044715f * x * x * x);
    return 0.5f * x * (1.0f + tanhf(u));
}

// ---------------- LayerNorm: one block per row, 256 threads, float4 ----------------
__global__ void __launch_bounds__(256) ln_kernel(const float* __restrict__ x,
                                                 const float* __restrict__ g,
                                                 const float* __restrict__ b,
                                                 float* __restrict__ out) {
    int row = blockIdx.x;
    int t = threadIdx.x;
    const float4* x4 = reinterpret_cast<const float4*>(x + (size_t)row * DMODEL);
    float4 v = x4[t];
    float s  = v.x + v.y + v.z + v.w;
    float ss = v.x * v.x + v.y * v.y + v.z * v.z + v.w * v.w;
    #pragma unroll
    for (int o = 16; o > 0; o >>= 1) {
        s  += __shfl_xor_sync(0xffffffffu, s, o);
        ss += __shfl_xor_sync(0xffffffffu, ss, o);
    }
    __shared__ float shs[8], shss[8];
    int warp = t >> 5, lane = t & 31;
    if (lane == 0) { shs[warp] = s; shss[warp] = ss; }
    __syncthreads();
    float tot = 0.f, tot2 = 0.f;
    #pragma unroll
    for (int i = 0; i < 8; i++) { tot += shs[i]; tot2 += shss[i]; }
    float mu   = tot * (1.0f / DMODEL);
    float var  = tot2 * (1.0f / DMODEL) - mu * mu;
    float rstd = rsqrtf(var + 1e-5f);
    float4 gv = reinterpret_cast<const float4*>(g)[t];
    float4 bv = reinterpret_cast<const float4*>(b)[t];
    float4 o;
    o.x = (v.x - mu) * rstd * gv.x + bv.x;
    o.y = (v.y - mu) * rstd * gv.y + bv.y;
    o.z = (v.z - mu) * rstd * gv.z + bv.z;
    o.w = (v.w - mu) * rstd * gv.w + bv.w;
    reinterpret_cast<float4*>(out + (size_t)row * DMODEL)[t] = o;
}

// ---------------- SGEMM: C = act(A@B + bias) [+ resid], 128x128x16, 8x8/thread ----------------
template<int ACT, int RESID>
__global__ void __launch_bounds__(256) sgemm_kernel(
    const float* __restrict__ A, const float* __restrict__ Bm,
    const float* __restrict__ bias, const float* __restrict__ Rm,
    float* __restrict__ C, int M, int N, int K)
{
    __shared__ float As[16][132];   // A tile transposed, padded
    __shared__ float Bs[16][128];
    const int row0 = blockIdx.y * 128;
    const int col0 = blockIdx.x * 128;
    const int t  = threadIdx.x;
    const int tx = t & 15;
    const int ty = t >> 4;
    float acc[8][8];
    #pragma unroll
    for (int i = 0; i < 8; i++)
        #pragma unroll
        for (int j = 0; j < 8; j++) acc[i][j] = 0.f;

    for (int kt = 0; kt < K; kt += 16) {
        #pragma unroll
        for (int u = 0; u < 2; u++) {
            int idx = t + u * 256;                 // 0..511
            int ar = idx >> 2;                     // 0..127
            int ac = (idx & 3) << 2;               // 0,4,8,12
            float4 av = *reinterpret_cast<const float4*>(
                A + (size_t)(row0 + ar) * K + kt + ac);
            As[ac + 0][ar] = av.x;
            As[ac + 1][ar] = av.y;
            As[ac + 2][ar] = av.z;
            As[ac + 3][ar] = av.w;
            int br = idx >> 5;                     // 0..15
            int bc = (idx & 31) << 2;              // 0..124
            *reinterpret_cast<float4*>(&Bs[br][bc]) =
                *reinterpret_cast<const float4*>(Bm + (size_t)(kt + br) * N + col0 + bc);
        }
        __syncthreads();
        #pragma unroll
        for (int k = 0; k < 16; k++) {
            float af[8], bf[8];
            *reinterpret_cast<float4*>(af)     = *reinterpret_cast<float4*>(&As[k][ty * 4]);
            *reinterpret_cast<float4*>(af + 4) = *reinterpret_cast<float4*>(&As[k][64 + ty * 4]);
            *reinterpret_cast<float4*>(bf)     = *reinterpret_cast<float4*>(&Bs[k][tx * 4]);
            *reinterpret_cast<float4*>(bf + 4) = *reinterpret_cast<float4*>(&Bs[k][64 + tx * 4]);
            #pragma unroll
            for (int i = 0; i < 8; i++)
                #pragma unroll
                for (int j = 0; j < 8; j++)
                    acc[i][j] = fmaf(af[i], bf[j], acc[i][j]);
        }
        __syncthreads();
    }

    #pragma unroll
    for (int i = 0; i < 8; i++) {
        int row = row0 + ((i < 4) ? (ty * 4 + i) : (64 + ty * 4 + (i - 4)));
        #pragma unroll
        for (int jh = 0; jh < 2; jh++) {
            int col = col0 + jh * 64 + tx * 4;
            float4 bv = *reinterpret_cast<const float4*>(bias + col);
            float4 o;
            o.x = acc[i][jh * 4 + 0] + bv.x;
            o.y = acc[i][jh * 4 + 1] + bv.y;
            o.z = acc[i][jh * 4 + 2] + bv.z;
            o.w = acc[i][jh * 4 + 3] + bv.w;
            if (ACT == 1) {
                o.x = gelu_new_f(o.x); o.y = gelu_new_f(o.y);
                o.z = gelu_new_f(o.z); o.w = gelu_new_f(o.w);
            }
            if (RESID) {
                float4 rv = *reinterpret_cast<const float4*>(Rm + (size_t)row * N + col);
                o.x += rv.x; o.y += rv.y; o.z += rv.z; o.w += rv.w;
            }
            *reinterpret_cast<float4*>(C + (size_t)row * N + col) = o;
        }
    }
}

// ---------------- Flash attention (fp32): BQ=64, BK=32, 4 threads per q-row ----------------
__global__ void __launch_bounds__(256) attn_kernel(const float* __restrict__ qkv,
                                                   float* __restrict__ out)
{
    __shared__ float Qs[64][68];
    __shared__ float Ks[32][68];
    __shared__ float Vs[32][68];
    __shared__ float Ps[64][33];

    const int qt = blockIdx.x;
    const int h  = blockIdx.y;
    const int b  = blockIdx.z;
    const int q0 = qt * 64;
    const int t  = threadIdx.x;
    const int r  = t >> 2;   // q row within tile (0..63)
    const int g  = t & 3;    // 4-thread group within row

    // Load Q tile [64, 64]
    #pragma unroll
    for (int u = 0; u < 4; u++) {
        int idx = t + u * 256;           // 0..1023
        int rr = idx >> 4;
        int c4 = (idx & 15) << 2;
        float4 v = *reinterpret_cast<const float4*>(
            qkv + (size_t)(b * SEQ + q0 + rr) * TD + h * DHEAD + c4);
        Qs[rr][c4 + 0] = v.x; Qs[rr][c4 + 1] = v.y;
        Qs[rr][c4 + 2] = v.z; Qs[rr][c4 + 3] = v.w;
    }

    float O[16];
    #pragma unroll
    for (int i = 0; i < 16; i++) O[i] = 0.f;
    float m = -1e30f, l = 0.f;

    const int jmax = (q0 + 63) >> 5;   // inclusive
    for (int j = 0; j <= jmax; j++) {
        __syncthreads();   // previous AV done reading Vs (and Q ready on first iter)
        #pragma unroll
        for (int u = 0; u < 2; u++) {
            int idx = t + u * 256;       // 0..511
            int rr = idx >> 4;
            int c4 = (idx & 15) << 2;
            size_t base = (size_t)(b * SEQ + j * 32 + rr) * TD + h * DHEAD + c4;
            float4 kv = *reinterpret_cast<const float4*>(qkv + base + DMODEL);
            Ks[rr][c4 + 0] = kv.x; Ks[rr][c4 + 1] = kv.y;
            Ks[rr][c4 + 2] = kv.z; Ks[rr][c4 + 3] = kv.w;
            float4 vv = *reinterpret_cast<const float4*>(qkv + base + 2 * DMODEL);
            Vs[rr][c4 + 0] = vv.x; Vs[rr][c4 + 1] = vv.y;
            Vs[rr][c4 + 2] = vv.z; Vs[rr][c4 + 3] = vv.w;
        }
        __syncthreads();

        // Scores: thread (r,g) computes cols {cc*4+g} — conflict-free Ks reads
        float s[8];
        #pragma unroll
        for (int cc = 0; cc < 8; cc++) s[cc] = 0.f;
        #pragma unroll
        for (int d = 0; d < 64; d += 4) {
            float4 qv = *reinterpret_cast<float4*>(&Qs[r][d]);
            #pragma unroll
            for (int cc = 0; cc < 8; cc++) {
                float4 kv = *reinterpret_cast<float4*>(&Ks[cc * 4 + g][d]);
                s[cc] += qv.x * kv.x + qv.y * kv.y + qv.z * kv.z + qv.w * kv.w;
            }
        }
        // Scale + causal mask
        float rowmax = -1e30f;
        #pragma unroll
        for (int cc = 0; cc < 8; cc++) {
            int kidx = j * 32 + cc * 4 + g;
            s[cc] = (kidx <= q0 + r) ? s[cc] * 0.125f : -1e30f;
            rowmax = fmaxf(rowmax, s[cc]);
        }
        rowmax = fmaxf(rowmax, __shfl_xor_sync(0xffffffffu, rowmax, 1));
        rowmax = fmaxf(rowmax, __shfl_xor_sync(0xffffffffu, rowmax, 2));
        float mnew = fmaxf(m, rowmax);
        float corr = __expf(m - mnew);
        float rs = 0.f;
        #pragma unroll
        for (int cc = 0; cc < 8; cc++) {
            float p = __expf(s[cc] - mnew);
            Ps[r][cc * 4 + g] = p;
            rs += p;
        }
        rs += __shfl_xor_sync(0xffffffffu, rs, 1);
        rs += __shfl_xor_sync(0xffffffffu, rs, 2);
        l = l * corr + rs;
        m = mnew;
        #pragma unroll
        for (int i = 0; i < 16; i++) O[i] *= corr;
        __syncwarp();   // Ps row exchange is intra-warp (rows are 4-lane aligned)
        #pragma unroll
        for (int k = 0; k < 32; k++) {
            float p = Ps[r][k];
            #pragma unroll
            for (int i4 = 0; i4 < 4; i4++) {
                float4 vv = *reinterpret_cast<float4*>(&Vs[k][g * 16 + i4 * 4]);
                O[i4 * 4 + 0] += p * vv.x;
                O[i4 * 4 + 1] += p * vv.y;
                O[i4 * 4 + 2] += p * vv.z;
                O[i4 * 4 + 3] += p * vv.w;
            }
        }
    }

    float linv = 1.0f / l;
    float* orow = out + (size_t)(b * SEQ + q0 + r) * DMODEL + h * DHEAD + g * 16;
    #pragma unroll
    for (int i4 = 0; i4 < 4; i4++) {
        float4 o;
        o.x = O[i4 * 4 + 0] * linv; o.y = O[i4 * 4 + 1] * linv;
        o.z = O[i4 * 4 + 2] * linv; o.w = O[i4 * 4 + 3] * linv;
        *reinterpret_cast<float4*>(orow + i4 * 4) = o;
    }
}

extern "C" void kernel_launch(void* const* d_in, const int* in_sizes, int n_in,
                              void* d_out, int out_size) {
    const float* hidden = (const float*)d_in[0];
    const float* ln1_g  = (const float*)d_in[1];
    const float* ln1_b  = (const float*)d_in[2];
    const float* w_attn = (const float*)d_in[3];
    const float* b_attn = (const float*)d_in[4];
    const float* w_ap   = (const float*)d_in[5];
    const float* b_ap   = (const float*)d_in[6];
    const float* ln2_g  = (const float*)d_in[7];
    const float* ln2_b  = (const float*)d_in[8];
    const float* w_fc   = (const float*)d_in[9];
    const float* b_fc   = (const float*)d_in[10];
    const float* w_mp   = (const float*)d_in[11];
    const float* b_mp   = (const float*)d_in[12];
    float* out = (float*)d_out;

    float *ln_buf, *qkv_buf, *attn_buf, *h2_buf, *fc_buf;
    cudaGetSymbolAddress((void**)&ln_buf,   g_ln);
    cudaGetSymbolAddress((void**)&qkv_buf,  g_qkv);
    cudaGetSymbolAddress((void**)&attn_buf, g_attn);
    cudaGetSymbolAddress((void**)&h2_buf,   g_h2);
    cudaGetSymbolAddress((void**)&fc_buf,   g_fc);

    // x = LN1(hidden)
    ln_kernel<<<MTOK, 256>>>(hidden, ln1_g, ln1_b, ln_buf);
    // qkv = x @ w_attn + b_attn
    sgemm_kernel<0, 0><<<dim3(TD / 128, MTOK / 128), 256>>>(
        ln_buf, w_attn, b_attn, nullptr, qkv_buf, MTOK, TD, DMODEL);
    // a = causal_softmax(q k^T / 8) v   (heads merged into [M, D])
    attn_kernel<<<dim3(SEQ / 64, NHEAD, BATCH), 256>>>(qkv_buf, attn_buf);
    // h2 = hidden + a @ w_attn_proj + b_attn_proj
    sgemm_kernel<0, 1><<<dim3(DMODEL / 128, MTOK / 128), 256>>>(
        attn_buf, w_ap, b_ap, hidden, h2_buf, MTOK, DMODEL, DMODEL);
    // m = LN2(h2)
    ln_kernel<<<MTOK, 256>>>(h2_buf, ln2_g, ln2_b, ln_buf);
    // fc = gelu_new(m @ w_fc + b_fc)
    sgemm_kernel<1, 0><<<dim3(FFD / 128, MTOK / 128), 256>>>(
        ln_buf, w_fc, b_fc, nullptr, fc_buf, MTOK, FFD, DMODEL);
    // out = h2 + fc @ w_mlp_proj + b_mlp_proj
    sgemm_kernel<0, 1><<<dim3(DMODEL / 128, MTOK / 128), 256>>>(
        fc_buf, w_mp, b_mp, h2_buf, out, MTOK, DMODEL, FFD);
}

// round 10
// speedup vs baseline: 1.6214x; 1.6214x over previous
#include <cuda_runtime.h>
#include <math.h>
#include <cstdint>

#define MTOK   8192
#define DMODEL 1024
#define TD     3072
#define FFD    4096
#define NHEAD  16
#define DHEAD  64
#define SEQ    2048
#define BATCH  4

// ---------------- scratch (no cudaMalloc allowed) ----------------
__device__ float g_ln  [(size_t)MTOK * DMODEL];
__device__ float g_qkv [(size_t)MTOK * TD];
__device__ float g_attn[(size_t)MTOK * DMODEL];
__device__ float g_h2  [(size_t)MTOK * DMODEL];
__device__ float g_fc  [(size_t)MTOK * FFD];
// transposed (and tf32-rounded) weights [N, K]
__device__ float g_wta [(size_t)TD * DMODEL];
__device__ float g_wtap[(size_t)DMODEL * DMODEL];
__device__ float g_wtfc[(size_t)FFD * DMODEL];
__device__ float g_wtmp[(size_t)DMODEL * FFD];

__device__ __forceinline__ float gelu_new_f(float x) {
    float u = 0.7978845608028654f * (x + 0.044715f * x * x * x);
    return 0.5f * x * (1.0f + tanhf(u));
}
__device__ __forceinline__ float to_tf32(float x) {
    uint32_t y;
    asm("cvt.rna.tf32.f32 %0, %1;" : "=r"(y) : "f"(x));
    return __uint_as_float(y);
}
__device__ __forceinline__ void cp16(uint32_t dst, const void* src) {
    asm volatile("cp.async.cg.shared.global [%0], [%1], 16;" :: "r"(dst), "l"(src));
}
__device__ __forceinline__ void mma_tf32(float* d, const uint32_t* a,
                                         uint32_t b0, uint32_t b1) {
    asm volatile(
        "mma.sync.aligned.m16n8k8.row.col.f32.tf32.tf32.f32 "
        "{%0,%1,%2,%3}, {%4,%5,%6,%7}, {%8,%9}, {%0,%1,%2,%3};"
        : "+f"(d[0]), "+f"(d[1]), "+f"(d[2]), "+f"(d[3])
        : "r"(a[0]), "r"(a[1]), "r"(a[2]), "r"(a[3]), "r"(b0), "r"(b1));
}

// ---------------- mma.sync tf32 GEMM: C[M,N] = act(A[M,K] @ Bt[N,K]^T + bias) [+R] ----
// CTA tile 128x128, BK=32, 256 threads = 8 warps (2x4), warp tile 64x32.
// Smem per stage: A 128x36f + B 128x36f (pad 36 -> conflict-free fragment LDS).
#define SROW   36
#define STAGEF (2 * 128 * SROW)          // floats per stage (A then B)
#define GEMM_SMEM (2 * STAGEF * 4)       // 73728 bytes, 2 stages

template<int ACT, int RESID, int CVT>
__global__ void __launch_bounds__(256, 2)
tc_gemm(const float* __restrict__ A, const float* __restrict__ Bt,
        const float* __restrict__ bias, const float* __restrict__ Rm,
        float* __restrict__ C, int N, int K)
{
    extern __shared__ float sm[];
    const int t = threadIdx.x;
    const int wid = t >> 5, lane = t & 31;
    const int g = lane >> 2, q = lane & 3;
    const int wm = wid >> 2, wn = wid & 3;
    const int row0 = blockIdx.y * 128;
    const int col0 = blockIdx.x * 128;

    const uint32_t smb = (uint32_t)__cvta_generic_to_shared(sm);
    const float* Ag0 = A  + (size_t)row0 * K;
    const float* Bg0 = Bt + (size_t)col0 * K;
    // per-thread load geometry: 4 chunks per tile per matrix
    const int lr0 = t >> 3;          // row 0..31 (stride 32)
    const int lch = t & 7;           // 16B chunk 0..7

    float acc[4][4][4];
    #pragma unroll
    for (int i = 0; i < 4; i++)
        #pragma unroll
        for (int j = 0; j < 4; j++)
            #pragma unroll
            for (int e = 0; e < 4; e++) acc[i][j][e] = 0.f;

    const int T = K >> 5;

    // ---- load tile kt into stage ----
    auto load_tile = [&](int kt, int stage) {
        uint32_t db = smb + stage * (STAGEF * 4);
        const float* Ap = Ag0 + kt * 32;
        const float* Bp = Bg0 + kt * 32;
        #pragma unroll
        for (int u = 0; u < 4; u++) {
            int r = lr0 + u * 32;
            uint32_t off = (uint32_t)(r * SROW + lch * 4) * 4u;
            cp16(db + off, Ap + (size_t)r * K + lch * 4);
            cp16(db + 128 * SROW * 4 + off, Bp + (size_t)r * K + lch * 4);
        }
    };

    // ---- compute on stage ----
    auto compute = [&](int stage) {
        const float* sA = sm + stage * STAGEF + (wm * 64 + g) * SROW;
        const float* sB = sm + stage * STAGEF + 128 * SROW + (wn * 32 + g) * SROW;
        #pragma unroll
        for (int k0 = 0; k0 < 4; k0++) {
            const int kc = k0 * 8 + q;
            uint32_t af[4][4];
            #pragma unroll
            for (int mt = 0; mt < 4; mt++) {
                af[mt][0] = __float_as_uint(sA[(mt * 16) * SROW + kc]);
                af[mt][1] = __float_as_uint(sA[(mt * 16 + 8) * SROW + kc]);
                af[mt][2] = __float_as_uint(sA[(mt * 16) * SROW + kc + 4]);
                af[mt][3] = __float_as_uint(sA[(mt * 16 + 8) * SROW + kc + 4]);
            }
            #pragma unroll
            for (int nt = 0; nt < 4; nt++) {
                uint32_t b0 = __float_as_uint(sB[(nt * 8) * SROW + kc]);
                uint32_t b1 = __float_as_uint(sB[(nt * 8) * SROW + kc + 4]);
                #pragma unroll
                for (int mt = 0; mt < 4; mt++)
                    mma_tf32(acc[mt][nt], af[mt], b0, b1);
            }
        }
    };

    load_tile(0, 0);
    asm volatile("cp.async.commit_group;");
    for (int kt = 0; kt < T; kt++) {
        if (kt + 1 < T) load_tile(kt + 1, (kt + 1) & 1);
        asm volatile("cp.async.commit_group;");
        asm volatile("cp.async.wait_group 1;");
        __syncthreads();
        compute(kt & 1);
        __syncthreads();
    }

    // ---- epilogue: fused bias/gelu/resid/cvt, float2 stores ----
    #pragma unroll
    for (int nt = 0; nt < 4; nt++) {
        const int c = col0 + wn * 32 + nt * 8 + 2 * q;
        const float2 bv = *reinterpret_cast<const float2*>(bias + c);
        #pragma unroll
        for (int mt = 0; mt < 4; mt++) {
            const int r0 = row0 + wm * 64 + mt * 16 + g;
            #pragma unroll
            for (int h = 0; h < 2; h++) {
                const int rr = r0 + h * 8;
                float x0 = acc[mt][nt][h * 2 + 0] + bv.x;
                float x1 = acc[mt][nt][h * 2 + 1] + bv.y;
                if (ACT) { x0 = gelu_new_f(x0); x1 = gelu_new_f(x1); }
                if (RESID) {
                    float2 rv = *reinterpret_cast<const float2*>(Rm + (size_t)rr * N + c);
                    x0 += rv.x; x1 += rv.y;
                }
                if (CVT) { x0 = to_tf32(x0); x1 = to_tf32(x1); }
                *reinterpret_cast<float2*>(C + (size_t)rr * N + c) = make_float2(x0, x1);
            }
        }
    }
}

// ---------------- 32x32 transpose + tf32 round: Wt[n][k] = tf32(W[k][n]) ----------------
__global__ void __launch_bounds__(256) transpose_kernel(const float* __restrict__ W,
                                                        float* __restrict__ Wt,
                                                        int K, int N) {
    __shared__ float tile[32][33];
    int bx = blockIdx.x * 32;   // N
    int by = blockIdx.y * 32;   // K
    int tx = threadIdx.x & 31, ty = threadIdx.x >> 5;
    #pragma unroll
    for (int i = 0; i < 32; i += 8)
        tile[ty + i][tx] = W[(size_t)(by + ty + i) * N + bx + tx];
    __syncthreads();
    #pragma unroll
    for (int i = 0; i < 32; i += 8)
        Wt[(size_t)(bx + ty + i) * K + by + tx] = to_tf32(tile[tx][ty + i]);
}

// ---------------- LayerNorm (output tf32-rounded: feeds GEMMs only) ----------------
__global__ void __launch_bounds__(256) ln_kernel(const float* __restrict__ x,
                                                 const float* __restrict__ g,
                                                 const float* __restrict__ b,
                                                 float* __restrict__ out) {
    int row = blockIdx.x;
    int t = threadIdx.x;
    const float4* x4 = reinterpret_cast<const float4*>(x + (size_t)row * DMODEL);
    float4 v = x4[t];
    float s  = v.x + v.y + v.z + v.w;
    float ss = v.x * v.x + v.y * v.y + v.z * v.z + v.w * v.w;
    #pragma unroll
    for (int o = 16; o > 0; o >>= 1) {
        s  += __shfl_xor_sync(0xffffffffu, s, o);
        ss += __shfl_xor_sync(0xffffffffu, ss, o);
    }
    __shared__ float shs[8], shss[8];
    int warp = t >> 5, lane = t & 31;
    if (lane == 0) { shs[warp] = s; shss[warp] = ss; }
    __syncthreads();
    float tot = 0.f, tot2 = 0.f;
    #pragma unroll
    for (int i = 0; i < 8; i++) { tot += shs[i]; tot2 += shss[i]; }
    float mu   = tot * (1.0f / DMODEL);
    float var  = tot2 * (1.0f / DMODEL) - mu * mu;
    float rstd = rsqrtf(var + 1e-5f);
    float4 gv = reinterpret_cast<const float4*>(g)[t];
    float4 bv = reinterpret_cast<const float4*>(b)[t];
    float4 o;
    o.x = to_tf32((v.x - mu) * rstd * gv.x + bv.x);
    o.y = to_tf32((v.y - mu) * rstd * gv.y + bv.y);
    o.z = to_tf32((v.z - mu) * rstd * gv.z + bv.z);
    o.w = to_tf32((v.w - mu) * rstd * gv.w + bv.w);
    reinterpret_cast<float4*>(out + (size_t)row * DMODEL)[t] = o;
}

// ---------------- Flash attention (fp32): BQ=64, BK=32, 4 threads per q-row ----------------
__global__ void __launch_bounds__(256) attn_kernel(const float* __restrict__ qkv,
                                                   float* __restrict__ out)
{
    __shared__ float Qs[64][68];
    __shared__ float Ks[32][68];
    __shared__ float Vs[32][68];
    __shared__ float Ps[64][33];

    const int qt = blockIdx.x;
    const int h  = blockIdx.y;
    const int b  = blockIdx.z;
    const int q0 = qt * 64;
    const int t  = threadIdx.x;
    const int r  = t >> 2;
    const int g  = t & 3;

    #pragma unroll
    for (int u = 0; u < 4; u++) {
        int idx = t + u * 256;
        int rr = idx >> 4;
        int c4 = (idx & 15) << 2;
        float4 v = *reinterpret_cast<const float4*>(
            qkv + (size_t)(b * SEQ + q0 + rr) * TD + h * DHEAD + c4);
        Qs[rr][c4 + 0] = v.x; Qs[rr][c4 + 1] = v.y;
        Qs[rr][c4 + 2] = v.z; Qs[rr][c4 + 3] = v.w;
    }

    float O[16];
    #pragma unroll
    for (int i = 0; i < 16; i++) O[i] = 0.f;
    float m = -1e30f, l = 0.f;

    const int jmax = (q0 + 63) >> 5;
    for (int j = 0; j <= jmax; j++) {
        __syncthreads();
        #pragma unroll
        for (int u = 0; u < 2; u++) {
            int idx = t + u * 256;
            int rr = idx >> 4;
            int c4 = (idx & 15) << 2;
            size_t base = (size_t)(b * SEQ + j * 32 + rr) * TD + h * DHEAD + c4;
            float4 kv = *reinterpret_cast<const float4*>(qkv + base + DMODEL);
            Ks[rr][c4 + 0] = kv.x; Ks[rr][c4 + 1] = kv.y;
            Ks[rr][c4 + 2] = kv.z; Ks[rr][c4 + 3] = kv.w;
            float4 vv = *reinterpret_cast<const float4*>(qkv + base + 2 * DMODEL);
            Vs[rr][c4 + 0] = vv.x; Vs[rr][c4 + 1] = vv.y;
            Vs[rr][c4 + 2] = vv.z; Vs[rr][c4 + 3] = vv.w;
        }
        __syncthreads();

        float s[8];
        #pragma unroll
        for (int cc = 0; cc < 8; cc++) s[cc] = 0.f;
        #pragma unroll
        for (int d = 0; d < 64; d += 4) {
            float4 qv = *reinterpret_cast<float4*>(&Qs[r][d]);
            #pragma unroll
            for (int cc = 0; cc < 8; cc++) {
                float4 kv = *reinterpret_cast<float4*>(&Ks[cc * 4 + g][d]);
                s[cc] += qv.x * kv.x + qv.y * kv.y + qv.z * kv.z + qv.w * kv.w;
            }
        }
        float rowmax = -1e30f;
        #pragma unroll
        for (int cc = 0; cc < 8; cc++) {
            int kidx = j * 32 + cc * 4 + g;
            s[cc] = (kidx <= q0 + r) ? s[cc] * 0.125f : -1e30f;
            rowmax = fmaxf(rowmax, s[cc]);
        }
        rowmax = fmaxf(rowmax, __shfl_xor_sync(0xffffffffu, rowmax, 1));
        rowmax = fmaxf(rowmax, __shfl_xor_sync(0xffffffffu, rowmax, 2));
        float mnew = fmaxf(m, rowmax);
        float corr = __expf(m - mnew);
        float rs = 0.f;
        #pragma unroll
        for (int cc = 0; cc < 8; cc++) {
            float p = __expf(s[cc] - mnew);
            Ps[r][cc * 4 + g] = p;
            rs += p;
        }
        rs += __shfl_xor_sync(0xffffffffu, rs, 1);
        rs += __shfl_xor_sync(0xffffffffu, rs, 2);
        l = l * corr + rs;
        m = mnew;
        #pragma unroll
        for (int i = 0; i < 16; i++) O[i] *= corr;
        __syncwarp();
        #pragma unroll
        for (int k = 0; k < 32; k++) {
            float p = Ps[r][k];
            #pragma unroll
            for (int i4 = 0; i4 < 4; i4++) {
                float4 vv = *reinterpret_cast<float4*>(&Vs[k][g * 16 + i4 * 4]);
                O[i4 * 4 + 0] += p * vv.x;
                O[i4 * 4 + 1] += p * vv.y;
                O[i4 * 4 + 2] += p * vv.z;
                O[i4 * 4 + 3] += p * vv.w;
            }
        }
    }

    float linv = 1.0f / l;
    float* orow = out + (size_t)(b * SEQ + q0 + r) * DMODEL + h * DHEAD + g * 16;
    #pragma unroll
    for (int i4 = 0; i4 < 4; i4++) {
        float4 o;
        o.x = to_tf32(O[i4 * 4 + 0] * linv);   // feeds attn-proj GEMM only
        o.y = to_tf32(O[i4 * 4 + 1] * linv);
        o.z = to_tf32(O[i4 * 4 + 2] * linv);
        o.w = to_tf32(O[i4 * 4 + 3] * linv);
        *reinterpret_cast<float4*>(orow + i4 * 4) = o;
    }
}

extern "C" void kernel_launch(void* const* d_in, const int* in_sizes, int n_in,
                              void* d_out, int out_size) {
    const float* hidden = (const float*)d_in[0];
    const float* ln1_g  = (const float*)d_in[1];
    const float* ln1_b  = (const float*)d_in[2];
    const float* w_attn = (const float*)d_in[3];
    const float* b_attn = (const float*)d_in[4];
    const float* w_ap   = (const float*)d_in[5];
    const float* b_ap   = (const float*)d_in[6];
    const float* ln2_g  = (const float*)d_in[7];
    const float* ln2_b  = (const float*)d_in[8];
    const float* w_fc   = (const float*)d_in[9];
    const float* b_fc   = (const float*)d_in[10];
    const float* w_mp   = (const float*)d_in[11];
    const float* b_mp   = (const float*)d_in[12];
    float* out = (float*)d_out;

    float *ln_buf, *qkv_buf, *attn_buf, *h2_buf, *fc_buf;
    float *wta, *wtap, *wtfc, *wtmp;
    cudaGetSymbolAddress((void**)&ln_buf,   g_ln);
    cudaGetSymbolAddress((void**)&qkv_buf,  g_qkv);
    cudaGetSymbolAddress((void**)&attn_buf, g_attn);
    cudaGetSymbolAddress((void**)&h2_buf,   g_h2);
    cudaGetSymbolAddress((void**)&fc_buf,   g_fc);
    cudaGetSymbolAddress((void**)&wta,  g_wta);
    cudaGetSymbolAddress((void**)&wtap, g_wtap);
    cudaGetSymbolAddress((void**)&wtfc, g_wtfc);
    cudaGetSymbolAddress((void**)&wtmp, g_wtmp);

    cudaFuncSetAttribute(tc_gemm<0, 0, 0>, cudaFuncAttributeMaxDynamicSharedMemorySize, GEMM_SMEM);
    cudaFuncSetAttribute(tc_gemm<0, 1, 0>, cudaFuncAttributeMaxDynamicSharedMemorySize, GEMM_SMEM);
    cudaFuncSetAttribute(tc_gemm<1, 0, 1>, cudaFuncAttributeMaxDynamicSharedMemorySize, GEMM_SMEM);

    // weight transposes [K,N] -> [N,K], tf32-rounded
    transpose_kernel<<<dim3(TD / 32, DMODEL / 32), 256>>>(w_attn, wta, DMODEL, TD);
    transpose_kernel<<<dim3(DMODEL / 32, DMODEL / 32), 256>>>(w_ap, wtap, DMODEL, DMODEL);
    transpose_kernel<<<dim3(FFD / 32, DMODEL / 32), 256>>>(w_fc, wtfc, DMODEL, FFD);
    transpose_kernel<<<dim3(DMODEL / 32, FFD / 32), 256>>>(w_mp, wtmp, FFD, DMODEL);

    // x = LN1(hidden)
    ln_kernel<<<MTOK, 256>>>(hidden, ln1_g, ln1_b, ln_buf);
    // qkv = x @ w_attn + b_attn
    tc_gemm<0, 0, 0><<<dim3(TD / 128, MTOK / 128), 256, GEMM_SMEM>>>(
        ln_buf, wta, b_attn, nullptr, qkv_buf, TD, DMODEL);
    // a = causal_softmax(q k^T / 8) v
    attn_kernel<<<dim3(SEQ / 64, NHEAD, BATCH), 256>>>(qkv_buf, attn_buf);
    // h2 = hidden + a @ w_attn_proj + b_attn_proj
    tc_gemm<0, 1, 0><<<dim3(DMODEL / 128, MTOK / 128), 256, GEMM_SMEM>>>(
        attn_buf, wtap, b_ap, hidden, h2_buf, DMODEL, DMODEL);
    // m = LN2(h2)
    ln_kernel<<<MTOK, 256>>>(h2_buf, ln2_g, ln2_b, ln_buf);
    // fc = gelu_new(m @ w_fc + b_fc)   (output tf32-rounded: feeds final GEMM)
    tc_gemm<1, 0, 1><<<dim3(FFD / 128, MTOK / 128), 256, GEMM_SMEM>>>(
        ln_buf, wtfc, b_fc, nullptr, fc_buf, FFD, DMODEL);
    // out = h2 + fc @ w_mlp_proj + b_mlp_proj
    tc_gemm<0, 1, 0><<<dim3(DMODEL / 128, MTOK / 128), 256, GEMM_SMEM>>>(
        fc_buf, wtmp, b_mp, h2_buf, out, DMODEL, FFD);
}

// round 11
// speedup vs baseline: 4.5438x; 2.8024x over previous
#include <cuda_runtime.h>
#include <math.h>
#include <cstdint>

#define MTOK   8192
#define DMODEL 1024
#define TD     3072
#define FFD    4096
#define NHEAD  16
#define DHEAD  64
#define SEQ    2048
#define BATCH  4

// ---------------- scratch (no cudaMalloc allowed) ----------------
__device__ float g_ln  [(size_t)MTOK * DMODEL];
__device__ float g_qkv [(size_t)MTOK * TD];
__device__ float g_attn[(size_t)MTOK * DMODEL];
__device__ float g_h2  [(size_t)MTOK * DMODEL];
__device__ float g_fc  [(size_t)MTOK * FFD];
// transposed (and tf32-rounded) weights [N, K]
__device__ float g_wta [(size_t)TD * DMODEL];
__device__ float g_wtap[(size_t)DMODEL * DMODEL];
__device__ float g_wtfc[(size_t)FFD * DMODEL];
__device__ float g_wtmp[(size_t)DMODEL * FFD];

__device__ __forceinline__ float gelu_new_f(float x) {
    float u = 0.7978845608028654f * (x + 0.044715f * x * x * x);
    return 0.5f * x * (1.0f + tanhf(u));
}
__device__ __forceinline__ float to_tf32(float x) {
    uint32_t y;
    asm("cvt.rna.tf32.f32 %0, %1;" : "=r"(y) : "f"(x));
    return __uint_as_float(y);
}
__device__ __forceinline__ void cp16(uint32_t dst, const void* src) {
    asm volatile("cp.async.cg.shared.global [%0], [%1], 16;" :: "r"(dst), "l"(src));
}
__device__ __forceinline__ void mma_tf32(float* d, const uint32_t* a,
                                         uint32_t b0, uint32_t b1) {
    asm volatile(
        "mma.sync.aligned.m16n8k8.row.col.f32.tf32.tf32.f32 "
        "{%0,%1,%2,%3}, {%4,%5,%6,%7}, {%8,%9}, {%0,%1,%2,%3};"
        : "+f"(d[0]), "+f"(d[1]), "+f"(d[2]), "+f"(d[3])
        : "r"(a[0]), "r"(a[1]), "r"(a[2]), "r"(a[3]), "r"(b0), "r"(b1));
}

// ---------------- mma.sync tf32 GEMM: C[M,N] = act(A[M,K] @ Bt[N,K]^T + bias) [+R] ----
#define SROW   36
#define STAGEF (2 * 128 * SROW)
#define GEMM_SMEM (2 * STAGEF * 4)

template<int ACT, int RESID, int CVT>
__global__ void __launch_bounds__(256, 2)
tc_gemm(const float* __restrict__ A, const float* __restrict__ Bt,
        const float* __restrict__ bias, const float* __restrict__ Rm,
        float* __restrict__ C, int N, int K)
{
    extern __shared__ float sm[];
    const int t = threadIdx.x;
    const int wid = t >> 5, lane = t & 31;
    const int g = lane >> 2, q = lane & 3;
    const int wm = wid >> 2, wn = wid & 3;
    const int row0 = blockIdx.y * 128;
    const int col0 = blockIdx.x * 128;

    const uint32_t smb = (uint32_t)__cvta_generic_to_shared(sm);
    const float* Ag0 = A  + (size_t)row0 * K;
    const float* Bg0 = Bt + (size_t)col0 * K;
    const int lr0 = t >> 3;
    const int lch = t & 7;

    float acc[4][4][4];
    #pragma unroll
    for (int i = 0; i < 4; i++)
        #pragma unroll
        for (int j = 0; j < 4; j++)
            #pragma unroll
            for (int e = 0; e < 4; e++) acc[i][j][e] = 0.f;

    const int T = K >> 5;

    auto load_tile = [&](int kt, int stage) {
        uint32_t db = smb + stage * (STAGEF * 4);
        const float* Ap = Ag0 + kt * 32;
        const float* Bp = Bg0 + kt * 32;
        #pragma unroll
        for (int u = 0; u < 4; u++) {
            int r = lr0 + u * 32;
            uint32_t off = (uint32_t)(r * SROW + lch * 4) * 4u;
            cp16(db + off, Ap + (size_t)r * K + lch * 4);
            cp16(db + 128 * SROW * 4 + off, Bp + (size_t)r * K + lch * 4);
        }
    };

    auto compute = [&](int stage) {
        const float* sA = sm + stage * STAGEF + (wm * 64 + g) * SROW;
        const float* sB = sm + stage * STAGEF + 128 * SROW + (wn * 32 + g) * SROW;
        #pragma unroll
        for (int k0 = 0; k0 < 4; k0++) {
            const int kc = k0 * 8 + q;
            uint32_t af[4][4];
            #pragma unroll
            for (int mt = 0; mt < 4; mt++) {
                af[mt][0] = __float_as_uint(sA[(mt * 16) * SROW + kc]);
                af[mt][1] = __float_as_uint(sA[(mt * 16 + 8) * SROW + kc]);
                af[mt][2] = __float_as_uint(sA[(mt * 16) * SROW + kc + 4]);
                af[mt][3] = __float_as_uint(sA[(mt * 16 + 8) * SROW + kc + 4]);
            }
            #pragma unroll
            for (int nt = 0; nt < 4; nt++) {
                uint32_t b0 = __float_as_uint(sB[(nt * 8) * SROW + kc]);
                uint32_t b1 = __float_as_uint(sB[(nt * 8) * SROW + kc + 4]);
                #pragma unroll
                for (int mt = 0; mt < 4; mt++)
                    mma_tf32(acc[mt][nt], af[mt], b0, b1);
            }
        }
    };

    load_tile(0, 0);
    asm volatile("cp.async.commit_group;");
    for (int kt = 0; kt < T; kt++) {
        if (kt + 1 < T) load_tile(kt + 1, (kt + 1) & 1);
        asm volatile("cp.async.commit_group;");
        asm volatile("cp.async.wait_group 1;");
        __syncthreads();
        compute(kt & 1);
        __syncthreads();
    }

    #pragma unroll
    for (int nt = 0; nt < 4; nt++) {
        const int c = col0 + wn * 32 + nt * 8 + 2 * q;
        const float2 bv = *reinterpret_cast<const float2*>(bias + c);
        #pragma unroll
        for (int mt = 0; mt < 4; mt++) {
            const int r0 = row0 + wm * 64 + mt * 16 + g;
            #pragma unroll
            for (int h = 0; h < 2; h++) {
                const int rr = r0 + h * 8;
                float x0 = acc[mt][nt][h * 2 + 0] + bv.x;
                float x1 = acc[mt][nt][h * 2 + 1] + bv.y;
                if (ACT) { x0 = gelu_new_f(x0); x1 = gelu_new_f(x1); }
                if (RESID) {
                    float2 rv = *reinterpret_cast<const float2*>(Rm + (size_t)rr * N + c);
                    x0 += rv.x; x1 += rv.y;
                }
                if (CVT) { x0 = to_tf32(x0); x1 = to_tf32(x1); }
                *reinterpret_cast<float2*>(C + (size_t)rr * N + c) = make_float2(x0, x1);
            }
        }
    }
}

// ---------------- 32x32 transpose + tf32 round ----------------
__global__ void __launch_bounds__(256) transpose_kernel(const float* __restrict__ W,
                                                        float* __restrict__ Wt,
                                                        int K, int N) {
    __shared__ float tile[32][33];
    int bx = blockIdx.x * 32;
    int by = blockIdx.y * 32;
    int tx = threadIdx.x & 31, ty = threadIdx.x >> 5;
    #pragma unroll
    for (int i = 0; i < 32; i += 8)
        tile[ty + i][tx] = W[(size_t)(by + ty + i) * N + bx + tx];
    __syncthreads();
    #pragma unroll
    for (int i = 0; i < 32; i += 8)
        Wt[(size_t)(bx + ty + i) * K + by + tx] = to_tf32(tile[tx][ty + i]);
}

// ---------------- LayerNorm (tf32-rounded output; feeds GEMMs only) ----------------
__global__ void __launch_bounds__(256) ln_kernel(const float* __restrict__ x,
                                                 const float* __restrict__ g,
                                                 const float* __restrict__ b,
                                                 float* __restrict__ out) {
    int row = blockIdx.x;
    int t = threadIdx.x;
    const float4* x4 = reinterpret_cast<const float4*>(x + (size_t)row * DMODEL);
    float4 v = x4[t];
    float s  = v.x + v.y + v.z + v.w;
    float ss = v.x * v.x + v.y * v.y + v.z * v.z + v.w * v.w;
    #pragma unroll
    for (int o = 16; o > 0; o >>= 1) {
        s  += __shfl_xor_sync(0xffffffffu, s, o);
        ss += __shfl_xor_sync(0xffffffffu, ss, o);
    }
    __shared__ float shs[8], shss[8];
    int warp = t >> 5, lane = t & 31;
    if (lane == 0) { shs[warp] = s; shss[warp] = ss; }
    __syncthreads();
    float tot = 0.f, tot2 = 0.f;
    #pragma unroll
    for (int i = 0; i < 8; i++) { tot += shs[i]; tot2 += shss[i]; }
    float mu   = tot * (1.0f / DMODEL);
    float var  = tot2 * (1.0f / DMODEL) - mu * mu;
    float rstd = rsqrtf(var + 1e-5f);
    float4 gv = reinterpret_cast<const float4*>(g)[t];
    float4 bv = reinterpret_cast<const float4*>(b)[t];
    float4 o;
    o.x = to_tf32((v.x - mu) * rstd * gv.x + bv.x);
    o.y = to_tf32((v.y - mu) * rstd * gv.y + bv.y);
    o.z = to_tf32((v.z - mu) * rstd * gv.z + bv.z);
    o.w = to_tf32((v.w - mu) * rstd * gv.w + bv.w);
    reinterpret_cast<float4*>(out + (size_t)row * DMODEL)[t] = o;
}

// ---------------- Tensor-core flash attention: BQ=64, BK=64, 4 warps ----------------
// Smem: Ks[2][64][68], Vs[2][64][68], Ps[64][68]  (Ps also stages Q at start)
#define AROW 68
#define ATILE (64 * AROW)
#define ATT_SMEM (5 * ATILE * 4)

__global__ void __launch_bounds__(128) attn_tc(const float* __restrict__ qkv,
                                               float* __restrict__ out)
{
    extern __shared__ float sm[];
    float* Ks = sm;
    float* Vs = sm + 2 * ATILE;
    float* Ps = sm + 4 * ATILE;
    const uint32_t smb = (uint32_t)__cvta_generic_to_shared(sm);
    const uint32_t Kb = smb, Vb = smb + 2 * ATILE * 4;

    const int qt = blockIdx.x, h = blockIdx.y, b = blockIdx.z;
    const int q0 = qt * 64;
    const int t = threadIdx.x;
    const int wid = t >> 5, lane = t & 31;
    const int g = lane >> 2, q = lane & 3;
    const int m0 = wid * 16;

    // ---- stage Q into Ps (coalesced), then into A-fragments (scaled by 1/8) ----
    #pragma unroll
    for (int u = 0; u < 8; u++) {
        int idx = t + u * 128;
        int rr = idx >> 4;
        int c4 = (idx & 15) << 2;
        float4 v = *reinterpret_cast<const float4*>(
            qkv + (size_t)(b * SEQ + q0 + rr) * TD + h * DHEAD + c4);
        *reinterpret_cast<float4*>(&Ps[rr * AROW + c4]) = v;
    }
    __syncthreads();
    uint32_t qf[8][4];
    #pragma unroll
    for (int k0 = 0; k0 < 8; k0++) {
        int kc = k0 * 8 + q;
        qf[k0][0] = __float_as_uint(0.125f * Ps[(m0 + g) * AROW + kc]);
        qf[k0][1] = __float_as_uint(0.125f * Ps[(m0 + g + 8) * AROW + kc]);
        qf[k0][2] = __float_as_uint(0.125f * Ps[(m0 + g) * AROW + kc + 4]);
        qf[k0][3] = __float_as_uint(0.125f * Ps[(m0 + g + 8) * AROW + kc + 4]);
    }
    __syncthreads();   // Ps free for P use

    auto load_kv = [&](int j, int st) {
        const float* base = qkv + (size_t)(b * SEQ + j * 64) * TD + h * DHEAD;
        uint32_t ko = Kb + (uint32_t)(st * ATILE) * 4;
        uint32_t vo = Vb + (uint32_t)(st * ATILE) * 4;
        #pragma unroll
        for (int u = 0; u < 8; u++) {
            int idx = t + u * 128;
            int rr = idx >> 4;
            int c4 = (idx & 15) << 2;
            uint32_t so = (uint32_t)(rr * AROW + c4) * 4;
            const float* gp = base + (size_t)rr * TD + c4;
            cp16(ko + so, gp + DMODEL);
            cp16(vo + so, gp + 2 * DMODEL);
        }
        asm volatile("cp.async.commit_group;");
    };

    float oacc[8][4];
    #pragma unroll
    for (int nt = 0; nt < 8; nt++)
        #pragma unroll
        for (int e = 0; e < 4; e++) oacc[nt][e] = 0.f;
    float m_lo = -1e30f, m_hi = -1e30f, l_lo = 0.f, l_hi = 0.f;

    load_kv(0, 0);
    for (int j = 0; j <= qt; j++) {
        if (j < qt) {
            load_kv(j + 1, (j + 1) & 1);
            asm volatile("cp.async.wait_group 1;");
        } else {
            asm volatile("cp.async.wait_group 0;");
        }
        __syncthreads();
        const float* Kst = Ks + (j & 1) * ATILE;
        const float* Vst = Vs + (j & 1) * ATILE;

        // ---- S = Q K^T (scaled) ----
        float sacc[8][4];
        #pragma unroll
        for (int nt = 0; nt < 8; nt++)
            #pragma unroll
            for (int e = 0; e < 4; e++) sacc[nt][e] = 0.f;
        #pragma unroll
        for (int k0 = 0; k0 < 8; k0++) {
            const int kc = k0 * 8 + q;
            #pragma unroll
            for (int nt = 0; nt < 8; nt++) {
                uint32_t b0 = __float_as_uint(Kst[(nt * 8 + g) * AROW + kc]);
                uint32_t b1 = __float_as_uint(Kst[(nt * 8 + g) * AROW + kc + 4]);
                mma_tf32(sacc[nt], qf[k0], b0, b1);
            }
        }

        // ---- causal mask (diagonal tile only) ----
        if (j == qt) {
            #pragma unroll
            for (int nt = 0; nt < 8; nt++) {
                const int c0 = nt * 8 + 2 * q;
                if (c0     > m0 + g)     sacc[nt][0] = -1e30f;
                if (c0 + 1 > m0 + g)     sacc[nt][1] = -1e30f;
                if (c0     > m0 + g + 8) sacc[nt][2] = -1e30f;
                if (c0 + 1 > m0 + g + 8) sacc[nt][3] = -1e30f;
            }
        }

        // ---- online softmax (rows m0+g, m0+g+8) ----
        float mx0 = -1e30f, mx1 = -1e30f;
        #pragma unroll
        for (int nt = 0; nt < 8; nt++) {
            mx0 = fmaxf(mx0, fmaxf(sacc[nt][0], sacc[nt][1]));
            mx1 = fmaxf(mx1, fmaxf(sacc[nt][2], sacc[nt][3]));
        }
        mx0 = fmaxf(mx0, __shfl_xor_sync(0xffffffffu, mx0, 1));
        mx0 = fmaxf(mx0, __shfl_xor_sync(0xffffffffu, mx0, 2));
        mx1 = fmaxf(mx1, __shfl_xor_sync(0xffffffffu, mx1, 1));
        mx1 = fmaxf(mx1, __shfl_xor_sync(0xffffffffu, mx1, 2));
        const float mn0 = fmaxf(m_lo, mx0), mn1 = fmaxf(m_hi, mx1);
        const float cr0 = __expf(m_lo - mn0), cr1 = __expf(m_hi - mn1);
        float rs0 = 0.f, rs1 = 0.f;
        #pragma unroll
        for (int nt = 0; nt < 8; nt++) {
            float e0 = __expf(sacc[nt][0] - mn0);
            float e1 = __expf(sacc[nt][1] - mn0);
            float e2 = __expf(sacc[nt][2] - mn1);
            float e3 = __expf(sacc[nt][3] - mn1);
            rs0 += e0 + e1; rs1 += e2 + e3;
            const int c0 = nt * 8 + 2 * q;
            *reinterpret_cast<float2*>(&Ps[(m0 + g) * AROW + c0]) =
                make_float2(to_tf32(e0), to_tf32(e1));
            *reinterpret_cast<float2*>(&Ps[(m0 + g + 8) * AROW + c0]) =
                make_float2(to_tf32(e2), to_tf32(e3));
        }
        rs0 += __shfl_xor_sync(0xffffffffu, rs0, 1);
        rs0 += __shfl_xor_sync(0xffffffffu, rs0, 2);
        rs1 += __shfl_xor_sync(0xffffffffu, rs1, 1);
        rs1 += __shfl_xor_sync(0xffffffffu, rs1, 2);
        l_lo = l_lo * cr0 + rs0;
        l_hi = l_hi * cr1 + rs1;
        m_lo = mn0; m_hi = mn1;
        #pragma unroll
        for (int nt = 0; nt < 8; nt++) {
            oacc[nt][0] *= cr0; oacc[nt][1] *= cr0;
            oacc[nt][2] *= cr1; oacc[nt][3] *= cr1;
        }
        __syncwarp();   // Ps rows are warp-private; order write->read

        // ---- O += P V ----
        #pragma unroll
        for (int k0 = 0; k0 < 8; k0++) {
            const int kc = k0 * 8 + q;
            uint32_t pa[4];
            pa[0] = __float_as_uint(Ps[(m0 + g) * AROW + kc]);
            pa[1] = __float_as_uint(Ps[(m0 + g + 8) * AROW + kc]);
            pa[2] = __float_as_uint(Ps[(m0 + g) * AROW + kc + 4]);
            pa[3] = __float_as_uint(Ps[(m0 + g + 8) * AROW + kc + 4]);
            #pragma unroll
            for (int nt = 0; nt < 8; nt++) {
                uint32_t b0 = __float_as_uint(Vst[kc * AROW + nt * 8 + g]);
                uint32_t b1 = __float_as_uint(Vst[(kc + 4) * AROW + nt * 8 + g]);
                mma_tf32(oacc[nt], pa, b0, b1);
            }
        }
        __syncthreads();   // protect stage (j&1) before next prefetch overwrites it
    }

    // ---- epilogue (tf32-rounded: feeds attn-proj GEMM) ----
    const float li0 = 1.0f / l_lo, li1 = 1.0f / l_hi;
    const int r_lo = b * SEQ + q0 + m0 + g;
    #pragma unroll
    for (int nt = 0; nt < 8; nt++) {
        const int col = h * DHEAD + nt * 8 + 2 * q;
        *reinterpret_cast<float2*>(out + (size_t)r_lo * DMODEL + col) =
            make_float2(to_tf32(oacc[nt][0] * li0), to_tf32(oacc[nt][1] * li0));
        *reinterpret_cast<float2*>(out + (size_t)(r_lo + 8) * DMODEL + col) =
            make_float2(to_tf32(oacc[nt][2] * li1), to_tf32(oacc[nt][3] * li1));
    }
}

extern "C" void kernel_launch(void* const* d_in, const int* in_sizes, int n_in,
                              void* d_out, int out_size) {
    const float* hidden = (const float*)d_in[0];
    const float* ln1_g  = (const float*)d_in[1];
    const float* ln1_b  = (const float*)d_in[2];
    const float* w_attn = (const float*)d_in[3];
    const float* b_attn = (const float*)d_in[4];
    const float* w_ap   = (const float*)d_in[5];
    const float* b_ap   = (const float*)d_in[6];
    const float* ln2_g  = (const float*)d_in[7];
    const float* ln2_b  = (const float*)d_in[8];
    const float* w_fc   = (const float*)d_in[9];
    const float* b_fc   = (const float*)d_in[10];
    const float* w_mp   = (const float*)d_in[11];
    const float* b_mp   = (const float*)d_in[12];
    float* out = (float*)d_out;

    float *ln_buf, *qkv_buf, *attn_buf, *h2_buf, *fc_buf;
    float *wta, *wtap, *wtfc, *wtmp;
    cudaGetSymbolAddress((void**)&ln_buf,   g_ln);
    cudaGetSymbolAddress((void**)&qkv_buf,  g_qkv);
    cudaGetSymbolAddress((void**)&attn_buf, g_attn);
    cudaGetSymbolAddress((void**)&h2_buf,   g_h2);
    cudaGetSymbolAddress((void**)&fc_buf,   g_fc);
    cudaGetSymbolAddress((void**)&wta,  g_wta);
    cudaGetSymbolAddress((void**)&wtap, g_wtap);
    cudaGetSymbolAddress((void**)&wtfc, g_wtfc);
    cudaGetSymbolAddress((void**)&wtmp, g_wtmp);

    cudaFuncSetAttribute(tc_gemm<0, 0, 1>, cudaFuncAttributeMaxDynamicSharedMemorySize, GEMM_SMEM);
    cudaFuncSetAttribute(tc_gemm<0, 1, 0>, cudaFuncAttributeMaxDynamicSharedMemorySize, GEMM_SMEM);
    cudaFuncSetAttribute(tc_gemm<1, 0, 1>, cudaFuncAttributeMaxDynamicSharedMemorySize, GEMM_SMEM);
    cudaFuncSetAttribute(attn_tc, cudaFuncAttributeMaxDynamicSharedMemorySize, ATT_SMEM);

    // weight transposes [K,N] -> [N,K], tf32-rounded
    transpose_kernel<<<dim3(TD / 32, DMODEL / 32), 256>>>(w_attn, wta, DMODEL, TD);
    transpose_kernel<<<dim3(DMODEL / 32, DMODEL / 32), 256>>>(w_ap, wtap, DMODEL, DMODEL);
    transpose_kernel<<<dim3(FFD / 32, DMODEL / 32), 256>>>(w_fc, wtfc, DMODEL, FFD);
    transpose_kernel<<<dim3(DMODEL / 32, FFD / 32), 256>>>(w_mp, wtmp, FFD, DMODEL);

    // x = LN1(hidden)
    ln_kernel<<<MTOK, 256>>>(hidden, ln1_g, ln1_b, ln_buf);
    // qkv = x @ w_attn + b_attn   (tf32-rounded for attention MMAs)
    tc_gemm<0, 0, 1><<<dim3(TD / 128, MTOK / 128), 256, GEMM_SMEM>>>(
        ln_buf, wta, b_attn, nullptr, qkv_buf, TD, DMODEL);
    // a = causal_softmax(q k^T / 8) v   (tensor-core flash attention)
    attn_tc<<<dim3(SEQ / 64, NHEAD, BATCH), 128, ATT_SMEM>>>(qkv_buf, attn_buf);
    // h2 = hidden + a @ w_attn_proj + b_attn_proj
    tc_gemm<0, 1, 0><<<dim3(DMODEL / 128, MTOK / 128), 256, GEMM_SMEM>>>(
        attn_buf, wtap, b_ap, hidden, h2_buf, DMODEL, DMODEL);
    // m = LN2(h2)
    ln_kernel<<<MTOK, 256>>>(h2_buf, ln2_g, ln2_b, ln_buf);
    // fc = gelu_new(m @ w_fc + b_fc)
    tc_gemm<1, 0, 1><<<dim3(FFD / 128, MTOK / 128), 256, GEMM_SMEM>>>(
        ln_buf, wtfc, b_fc, nullptr, fc_buf, FFD, DMODEL);
    // out = h2 + fc @ w_mlp_proj + b_mlp_proj
    tc_gemm<0, 1, 0><<<dim3(DMODEL / 128, MTOK / 128), 256, GEMM_SMEM>>>(
        fc_buf, wtmp, b_mp, h2_buf, out, DMODEL, FFD);
}